// round 15
// baseline (speedup 1.0000x reference)
#include <cuda_runtime.h>
#include <cuda_bf16.h>
#include <math.h>
#include <stdint.h>

#define BB   8
#define NN   2048
#define DD   256
#define HH   8
#define HD   32
#define DFF  1024
#define TT   (BB*NN)
#define LDT  40              // attention smem row stride (32 data + 8 pad)
#define VLD  136             // V^T smem row stride (128 data + 8 pad)
#define LD64 72              // GEMM smem row stride (64 data + 8 pad)
#define QSC  (0.17677669529663687f * 1.4426950408889634f)   // 1/sqrt(32) * log2(e)

// ---------------- fp32 scratch ----------------
__device__ float g_y[TT*DD];
__device__ float g_x1[TT*DD];
__device__ float g_z[TT*DD];

// ---------------- bf16 scratch ----------------
__device__ __nv_bfloat16 xb[TT*DD];
__device__ __nv_bfloat16 qb[BB*HH*NN*HD];      // scaled by log2e/sqrt(HD)
__device__ __nv_bfloat16 kb[BB*HH*NN*HD];
__device__ __nv_bfloat16 vtb[BB*HH*HD*NN];     // V transposed: [B,H,HD,N]
__device__ __nv_bfloat16 ob[TT*DD];
__device__ __nv_bfloat16 yb[TT*DD];
__device__ __nv_bfloat16 fb[TT*DFF];
__device__ __nv_bfloat16 wqkvb[3*DD*DD];
__device__ __nv_bfloat16 woutb[DD*DD];
__device__ __nv_bfloat16 w1b[DFF*DD];
__device__ __nv_bfloat16 wvb[DFF*DD];
__device__ __nv_bfloat16 w2b[DD*DFF];

// ---------------- helpers ----------------
__device__ __forceinline__ uint32_t sm_u32(const void* p) {
    uint32_t a;
    asm("{ .reg .u64 t; cvta.to.shared.u64 t, %1; cvt.u32.u64 %0, t; }" : "=r"(a) : "l"(p));
    return a;
}
__device__ __forceinline__ void cpa16(uint32_t dst, const void* src) {
    asm volatile("cp.async.cg.shared.global [%0], [%1], 16;" :: "r"(dst), "l"(src));
}
__device__ __forceinline__ void cpa_commit() {
    asm volatile("cp.async.commit_group;" ::: "memory");
}
template<int N>
__device__ __forceinline__ void cpa_wait() {
    asm volatile("cp.async.wait_group %0;" :: "n"(N) : "memory");
}
__device__ __forceinline__ void ldm_x4(uint32_t* r, uint32_t addr) {
    asm volatile("ldmatrix.sync.aligned.m8n8.x4.shared.b16 {%0,%1,%2,%3}, [%4];"
                 : "=r"(r[0]), "=r"(r[1]), "=r"(r[2]), "=r"(r[3]) : "r"(addr));
}
__device__ __forceinline__ void mma_bf16(float* d, const uint32_t* a, const uint32_t* b) {
    asm volatile("mma.sync.aligned.m16n8k16.row.col.f32.bf16.bf16.f32 "
                 "{%0,%1,%2,%3}, {%4,%5,%6,%7}, {%8,%9}, {%0,%1,%2,%3};"
                 : "+f"(d[0]), "+f"(d[1]), "+f"(d[2]), "+f"(d[3])
                 : "r"(a[0]), "r"(a[1]), "r"(a[2]), "r"(a[3]), "r"(b[0]), "r"(b[1]));
}
__device__ __forceinline__ float ex2f(float x) {
    float y;
    asm("ex2.approx.f32 %0, %1;" : "=f"(y) : "f"(x));
    return y;
}
__device__ __forceinline__ uint32_t packbf(float a, float b) {
    __nv_bfloat162 t = __floats2bfloat162_rn(a, b);
    return *reinterpret_cast<uint32_t*>(&t);
}
__device__ __forceinline__ float gelu_f(float x) {
    return 0.5f * x * (1.0f + erff(x * 0.70710678118654752f));
}

// Async-load an R x 64 bf16 tile (row-major, ldk elems) into smem with LD64 stride.
template<int R>
__device__ __forceinline__ void ld_tile64(const __nv_bfloat16* __restrict__ src,
                                          size_t rowbase, int ldk,
                                          uint32_t smbase, int tid) {
    #pragma unroll
    for (int i = 0; i < R * 8 / 256; ++i) {
        int s = tid + i * 256;
        int r = s >> 3, cs = s & 7;
        cpa16(smbase + (r * LD64 + cs * 8) * 2,
              src + rowbase + (size_t)r * ldk + cs * 8);
    }
}

// ---------------- bf16 HMMA GEMM (BK=64, 2-stage pipeline, paired-x4 B loads) ----------------
// Block 128x128, 8 warps (2 M x 4 N), warp tile 64x32.
// EPI: 0 = QKV scatter, 1 = outproj(+bias), 2 = ffn2 -> g_z
template<int KTOT, int EPI>
__global__ void __launch_bounds__(256, 2) k_gemm(const float* __restrict__ bias) {
    extern __shared__ __nv_bfloat16 dsm[];
    constexpr int TSZ = 128 * LD64;
    const int tid = threadIdx.x, wid = tid >> 5, lane = tid & 31;
    const int wm = wid >> 2, wn = wid & 3;
    const int m0 = blockIdx.y * 128, n0 = blockIdx.x * 128;

    const __nv_bfloat16 *pA, *pB;
    if constexpr (EPI == 0)      { pA = xb; pB = wqkvb; }
    else if constexpr (EPI == 1) { pA = ob; pB = woutb; }
    else                         { pA = fb; pB = w2b;   }

    float acc[4][4][4] = {};
    uint32_t sA[2], sB[2];
    #pragma unroll
    for (int s = 0; s < 2; ++s) {
        sA[s] = sm_u32(dsm + s * TSZ);
        sB[s] = sm_u32(dsm + (2 + s) * TSZ);
    }
    const int a_row = wm * 64 + (lane & 15);
    const int a_k   = (lane >> 4) * 8;
    const int b_row4 = wn * 32 + ((lane >> 4) << 3) + (lane & 7);
    const int b_k    = ((lane >> 3) & 1) * 8;

    constexpr int NCH = KTOT / 64;
    ld_tile64<128>(pA, (size_t)m0 * KTOT, KTOT, sA[0], tid);
    ld_tile64<128>(pB, (size_t)n0 * KTOT, KTOT, sB[0], tid);
    cpa_commit();

    for (int c = 0; c < NCH; ++c) {
        if (c + 1 < NCH) {
            const int nb = (c + 1) & 1;
            ld_tile64<128>(pA, (size_t)m0 * KTOT + (c + 1) * 64, KTOT, sA[nb], tid);
            ld_tile64<128>(pB, (size_t)n0 * KTOT + (c + 1) * 64, KTOT, sB[nb], tid);
            cpa_commit();
            cpa_wait<1>();
        } else {
            cpa_wait<0>();
        }
        __syncthreads();
        const uint32_t bA = sA[c & 1], bB = sB[c & 1];
        #pragma unroll
        for (int ks = 0; ks < 64; ks += 16) {
            uint32_t fA[4][4], fB[2][4];
            #pragma unroll
            for (int mi = 0; mi < 4; ++mi)
                ldm_x4(fA[mi], bA + ((a_row + mi * 16) * LD64 + ks + a_k) * 2);
            #pragma unroll
            for (int p = 0; p < 2; ++p)
                ldm_x4(fB[p], bB + ((b_row4 + p * 16) * LD64 + ks + b_k) * 2);
            #pragma unroll
            for (int mi = 0; mi < 4; ++mi)
                #pragma unroll
                for (int ni = 0; ni < 4; ++ni)
                    mma_bf16(acc[mi][ni], fA[mi], &fB[ni >> 1][(ni & 1) * 2]);
        }
        __syncthreads();
    }

    #pragma unroll
    for (int mi = 0; mi < 4; ++mi) {
        #pragma unroll
        for (int ni = 0; ni < 4; ++ni) {
            const int r = m0 + wm * 64 + mi * 16 + (lane >> 2);
            const int cc = n0 + wn * 32 + ni * 8 + (lane & 3) * 2;
            #pragma unroll
            for (int half = 0; half < 2; ++half) {
                const int m = r + half * 8;
                const float v0 = acc[mi][ni][half * 2 + 0];
                const float v1 = acc[mi][ni][half * 2 + 1];
                if constexpr (EPI == 0) {
                    const int part = cc >> 8, hh = (cc >> 5) & 7, d = cc & 31;
                    const int b = m >> 11, nn = m & 2047;
                    const size_t bh = (size_t)(b * HH + hh);
                    if (part == 0) {
                        *reinterpret_cast<__nv_bfloat162*>(qb + (bh * NN + nn) * HD + d)
                            = __floats2bfloat162_rn(v0 * QSC, v1 * QSC);
                    } else if (part == 1) {
                        *reinterpret_cast<__nv_bfloat162*>(kb + (bh * NN + nn) * HD + d)
                            = __floats2bfloat162_rn(v0, v1);
                    } else {
                        vtb[(bh * HD + d)     * NN + nn] = __float2bfloat16(v0);
                        vtb[(bh * HD + d + 1) * NN + nn] = __float2bfloat16(v1);
                    }
                } else if constexpr (EPI == 1) {
                    const float y0 = v0 + bias[cc], y1 = v1 + bias[cc + 1];
                    *reinterpret_cast<float2*>(g_y + (size_t)m * DD + cc) = make_float2(y0, y1);
                    *reinterpret_cast<__nv_bfloat162*>(yb + (size_t)m * DD + cc)
                        = __floats2bfloat162_rn(y0, y1);
                } else {
                    *reinterpret_cast<float2*>(g_z + (size_t)m * DD + cc) = make_float2(v0, v1);
                }
            }
        }
    }
}

// ---------------- dual-B GEMM (GEGLU up, BK=64, paired-x4 B loads) ----------------
// Block 128x64, 8 warps (4 M x 2 N), warp tile 32x32.
__global__ void __launch_bounds__(256, 2) k_ffn1() {
    extern __shared__ __nv_bfloat16 dsm[];
    constexpr int ASZ = 128 * LD64, BSZ = 64 * LD64;
    const int tid = threadIdx.x, wid = tid >> 5, lane = tid & 31;
    const int wm = wid >> 1, wn = wid & 1;
    const int m0 = blockIdx.y * 128, n0 = blockIdx.x * 64;

    float acc1[2][4][4] = {}, acc2[2][4][4] = {};
    uint32_t sA[2], sB1[2], sB2[2];
    #pragma unroll
    for (int s = 0; s < 2; ++s) {
        sA[s]  = sm_u32(dsm + s * ASZ);
        sB1[s] = sm_u32(dsm + 2 * ASZ + s * BSZ);
        sB2[s] = sm_u32(dsm + 2 * ASZ + 2 * BSZ + s * BSZ);
    }
    const int a_row = wm * 32 + (lane & 15);
    const int a_k   = (lane >> 4) * 8;
    const int b_row4 = wn * 32 + ((lane >> 4) << 3) + (lane & 7);
    const int b_k    = ((lane >> 3) & 1) * 8;

    constexpr int NCH = DD / 64;
    auto ldchunk = [&](int c, int buf) {
        ld_tile64<128>(yb,  (size_t)m0 * DD + c * 64, DD, sA[buf],  tid);
        ld_tile64<64>(w1b,  (size_t)n0 * DD + c * 64, DD, sB1[buf], tid);
        ld_tile64<64>(wvb,  (size_t)n0 * DD + c * 64, DD, sB2[buf], tid);
        cpa_commit();
    };
    ldchunk(0, 0);

    for (int c = 0; c < NCH; ++c) {
        if (c + 1 < NCH) {
            ldchunk(c + 1, (c + 1) & 1);
            cpa_wait<1>();
        } else {
            cpa_wait<0>();
        }
        __syncthreads();
        const uint32_t bA = sA[c & 1], bB1 = sB1[c & 1], bB2 = sB2[c & 1];
        #pragma unroll
        for (int ks = 0; ks < 64; ks += 16) {
            uint32_t fA[2][4], f1[2][4], f2[2][4];
            #pragma unroll
            for (int mi = 0; mi < 2; ++mi)
                ldm_x4(fA[mi], bA + ((a_row + mi * 16) * LD64 + ks + a_k) * 2);
            #pragma unroll
            for (int p = 0; p < 2; ++p) {
                const uint32_t off = ((b_row4 + p * 16) * LD64 + ks + b_k) * 2;
                ldm_x4(f1[p], bB1 + off);
                ldm_x4(f2[p], bB2 + off);
            }
            #pragma unroll
            for (int mi = 0; mi < 2; ++mi)
                #pragma unroll
                for (int ni = 0; ni < 4; ++ni) {
                    mma_bf16(acc1[mi][ni], fA[mi], &f1[ni >> 1][(ni & 1) * 2]);
                    mma_bf16(acc2[mi][ni], fA[mi], &f2[ni >> 1][(ni & 1) * 2]);
                }
        }
        __syncthreads();
    }

    #pragma unroll
    for (int mi = 0; mi < 2; ++mi)
        #pragma unroll
        for (int ni = 0; ni < 4; ++ni) {
            const int r = m0 + wm * 32 + mi * 16 + (lane >> 2);
            const int cc = n0 + wn * 32 + ni * 8 + (lane & 3) * 2;
            #pragma unroll
            for (int half = 0; half < 2; ++half) {
                const int m = r + half * 8;
                const float f0 = gelu_f(acc1[mi][ni][half * 2]) * acc2[mi][ni][half * 2];
                const float f1 = gelu_f(acc1[mi][ni][half * 2 + 1]) * acc2[mi][ni][half * 2 + 1];
                *reinterpret_cast<__nv_bfloat162*>(fb + (size_t)m * DFF + cc)
                    = __floats2bfloat162_rn(f0, f1);
            }
        }
}

// ---------------- HMMA flash attention (256-query tiles; K/V fragments shared by 2 m-tiles) ----------------
__global__ void __launch_bounds__(256, 2) k_fattn() {
    __shared__ __nv_bfloat16 Qs[256 * LDT], Ks[2][128 * LDT], Vts[2][32 * VLD];
    const int tid = threadIdx.x, w = tid >> 5, lane = tid & 31;
    const int b = blockIdx.z, h = blockIdx.y, q0 = blockIdx.x * 256;
    const size_t bh = (size_t)(b * HH + h);
    const __nv_bfloat16* Qg = qb + bh * NN * HD + (size_t)q0 * HD;
    const __nv_bfloat16* Kg = kb + bh * NN * HD;
    const __nv_bfloat16* Vg = vtb + bh * HD * NN;

    #pragma unroll
    for (int i = 0; i < 4; ++i) {
        int s = tid + i * 256;
        int r = s >> 2, cs = s & 3;
        float4 v = *reinterpret_cast<const float4*>(Qg + (size_t)r * HD + cs * 8);
        *reinterpret_cast<float4*>(&Qs[r * LDT + cs * 8]) = v;
    }
    const uint32_t sQ = sm_u32(Qs);
    const uint32_t sK[2] = { sm_u32(Ks[0]),  sm_u32(Ks[1])  };
    const uint32_t sV[2] = { sm_u32(Vts[0]), sm_u32(Vts[1]) };

    auto ldkv = [&](int j0, int buf) {
        #pragma unroll
        for (int i = 0; i < 2; ++i) {
            int s = tid + i * 256;
            int r = s >> 2, cs = s & 3;
            cpa16(sK[buf] + (r * LDT + cs * 8) * 2, Kg + (size_t)(j0 + r) * HD + cs * 8);
        }
        #pragma unroll
        for (int i = 0; i < 2; ++i) {
            int s = tid + i * 256;
            int r = s >> 4, cs = s & 15;
            cpa16(sV[buf] + (r * VLD + cs * 8) * 2, Vg + (size_t)r * NN + j0 + cs * 8);
        }
        cpa_commit();
    };
    ldkv(0, 0);

    __syncthreads();
    // Each warp owns two 16-row m-tiles: rows w*16 and 128 + w*16.
    uint32_t qA[2][2][4];   // [mt][ks]
    {
        const int ak = (lane >> 4) * 8;
        #pragma unroll
        for (int mt = 0; mt < 2; ++mt) {
            const int arow = mt * 128 + w * 16 + (lane & 15);
            ldm_x4(qA[mt][0], sQ + (arow * LDT + ak) * 2);
            ldm_x4(qA[mt][1], sQ + (arow * LDT + 16 + ak) * 2);
        }
    }

    float l[2][2] = {};         // [mt][rowhalf]
    float Of[2][4][4] = {};     // [mt][nf][frag]
    const int b_row4 = ((lane >> 4) << 3) + (lane & 7);
    const int b_k    = ((lane >> 3) & 1) * 8;

    for (int j0 = 0; j0 < NN; j0 += 128) {
        cpa_wait<0>();
        __syncthreads();
        if (j0 + 128 < NN) ldkv(j0 + 128, ((j0 >> 7) + 1) & 1);
        const int bf = (j0 >> 7) & 1;

        // S' for both m-tiles: one K ldm_x4 feeds 4 MMAs (2 m-tiles x 2 n-subtiles)
        float sf[2][16][4];     // [mt][ni][frag] -- big but transient per phase
        #pragma unroll
        for (int p = 0; p < 8; ++p) {
            #pragma unroll
            for (int mt = 0; mt < 2; ++mt) {
                sf[mt][2*p][0] = sf[mt][2*p][1] = sf[mt][2*p][2] = sf[mt][2*p][3] = 0.f;
                sf[mt][2*p+1][0] = sf[mt][2*p+1][1] = sf[mt][2*p+1][2] = sf[mt][2*p+1][3] = 0.f;
            }
            #pragma unroll
            for (int ks = 0; ks < 2; ++ks) {
                uint32_t bb[4];
                ldm_x4(bb, sK[bf] + ((p * 16 + b_row4) * LDT + ks * 16 + b_k) * 2);
                #pragma unroll
                for (int mt = 0; mt < 2; ++mt) {
                    mma_bf16(sf[mt][2*p],     qA[mt][ks], &bb[0]);
                    mma_bf16(sf[mt][2*p + 1], qA[mt][ks], &bb[2]);
                }
            }
        }

        // exp + PV, one kf strip at a time; V fragments shared by both m-tiles
        #pragma unroll
        for (int kf = 0; kf < 8; ++kf) {
            uint32_t pa[2][4];
            #pragma unroll
            for (int mt = 0; mt < 2; ++mt) {
                const float p00 = ex2f(sf[mt][2 * kf][0]);
                const float p01 = ex2f(sf[mt][2 * kf][1]);
                const float p10 = ex2f(sf[mt][2 * kf][2]);
                const float p11 = ex2f(sf[mt][2 * kf][3]);
                const float p20 = ex2f(sf[mt][2 * kf + 1][0]);
                const float p21 = ex2f(sf[mt][2 * kf + 1][1]);
                const float p30 = ex2f(sf[mt][2 * kf + 1][2]);
                const float p31 = ex2f(sf[mt][2 * kf + 1][3]);
                l[mt][0] += p00 + p01 + p20 + p21;
                l[mt][1] += p10 + p11 + p30 + p31;
                pa[mt][0] = packbf(p00, p01);
                pa[mt][1] = packbf(p10, p11);
                pa[mt][2] = packbf(p20, p21);
                pa[mt][3] = packbf(p30, p31);
            }
            #pragma unroll
            for (int pp = 0; pp < 2; ++pp) {
                uint32_t vv[4];
                ldm_x4(vv, sV[bf] + ((pp * 16 + b_row4) * VLD + kf * 16 + b_k) * 2);
                #pragma unroll
                for (int mt = 0; mt < 2; ++mt) {
                    mma_bf16(Of[mt][2 * pp],     pa[mt], &vv[0]);
                    mma_bf16(Of[mt][2 * pp + 1], pa[mt], &vv[2]);
                }
            }
        }
    }

    #pragma unroll
    for (int mt = 0; mt < 2; ++mt) {
        l[mt][0] += __shfl_xor_sync(0xffffffffu, l[mt][0], 1);
        l[mt][0] += __shfl_xor_sync(0xffffffffu, l[mt][0], 2);
        l[mt][1] += __shfl_xor_sync(0xffffffffu, l[mt][1], 1);
        l[mt][1] += __shfl_xor_sync(0xffffffffu, l[mt][1], 2);
        const float i0 = 1.0f / l[mt][0], i1 = 1.0f / l[mt][1];
        const int t0 = b * NN + q0 + mt * 128 + w * 16 + (lane >> 2);
        const int c2 = (lane & 3) * 2;
        #pragma unroll
        for (int nf = 0; nf < 4; ++nf) {
            const int d = h * HD + nf * 8 + c2;
            *reinterpret_cast<__nv_bfloat162*>(ob + (size_t)t0 * DD + d)
                = __floats2bfloat162_rn(Of[mt][nf][0] * i0, Of[mt][nf][1] * i0);
            *reinterpret_cast<__nv_bfloat162*>(ob + (size_t)(t0 + 8) * DD + d)
                = __floats2bfloat162_rn(Of[mt][nf][2] * i1, Of[mt][nf][3] * i1);
        }
    }
}

// ---------------- merged fp32 -> bf16 conversion ----------------
#define C_X   (TT*DD/4)
#define C_QKV (3*DD*DD/4)
#define C_OUT (DD*DD/4)
#define C_W1  (DFF*DD/4)
#define CVT_TOT (C_X + C_QKV + C_OUT + 3*C_W1)
__global__ void __launch_bounds__(256) k_cvt_all(const float* __restrict__ x,
                                                 const float* __restrict__ wq,
                                                 const float* __restrict__ wo,
                                                 const float* __restrict__ w1,
                                                 const float* __restrict__ wv,
                                                 const float* __restrict__ w2) {
    int i = blockIdx.x * 256 + threadIdx.x;
    if (i >= CVT_TOT) return;
    const float* s;
    __nv_bfloat16* d;
    int o = i;
    if (o < C_X)                      { s = x;  d = xb;    }
    else if ((o -= C_X)   < C_QKV)    { s = wq; d = wqkvb; }
    else if ((o -= C_QKV) < C_OUT)    { s = wo; d = woutb; }
    else if ((o -= C_OUT) < C_W1)     { s = w1; d = w1b;   }
    else if ((o -= C_W1)  < C_W1)     { s = wv; d = wvb;   }
    else                              { o -= C_W1; s = w2; d = w2b; }
    float4 v = reinterpret_cast<const float4*>(s)[o];
    reinterpret_cast<__nv_bfloat162*>(d)[2 * o]     = __floats2bfloat162_rn(v.x, v.y);
    reinterpret_cast<__nv_bfloat162*>(d)[2 * o + 1] = __floats2bfloat162_rn(v.z, v.w);
}

// ---------------- warp-per-row Add + LayerNorm ----------------
__device__ __forceinline__ void ln_row(const float* __restrict__ pa,
                                       const float* __restrict__ pb,
                                       const float* __restrict__ g,
                                       const float* __restrict__ beta,
                                       float* __restrict__ out, int lane) {
    float vals[8];
    float s = 0.f, s2 = 0.f;
    #pragma unroll
    for (int i = 0; i < 8; ++i) {
        float v = pa[lane + i * 32] + pb[lane + i * 32];
        vals[i] = v; s += v; s2 += v * v;
    }
    #pragma unroll
    for (int off = 16; off >= 1; off >>= 1) {
        s  += __shfl_xor_sync(0xffffffffu, s, off);
        s2 += __shfl_xor_sync(0xffffffffu, s2, off);
    }
    const float mean = s * (1.0f / DD);
    const float var = s2 * (1.0f / DD) - mean * mean;
    const float inv = rsqrtf(var + 1e-5f);
    #pragma unroll
    for (int i = 0; i < 8; ++i) {
        const int c = lane + i * 32;
        out[c] = (vals[i] - mean) * inv * g[c] + beta[c];
    }
}

__global__ void __launch_bounds__(256) k_ln1(const float* __restrict__ x,
                                             const float* __restrict__ g,
                                             const float* __restrict__ beta) {
    const int row = blockIdx.x * 8 + (threadIdx.x >> 5);
    const int lane = threadIdx.x & 31;
    ln_row(g_y + (size_t)row * DD, x + (size_t)row * DD, g, beta,
           g_x1 + (size_t)row * DD, lane);
}

__global__ void __launch_bounds__(256) k_ln2(const float* __restrict__ g,
                                             const float* __restrict__ beta,
                                             float* __restrict__ out) {
    const int row = blockIdx.x * 8 + (threadIdx.x >> 5);
    const int lane = threadIdx.x & 31;
    ln_row(g_z + (size_t)row * DD, g_x1 + (size_t)row * DD, g, beta,
           out + (size_t)row * DD, lane);
}

// ---------------- launch ----------------
extern "C" void kernel_launch(void* const* d_in, const int* in_sizes, int n_in,
                              void* d_out, int out_size) {
    const float* x     = (const float*)d_in[0];
    const float* w_qkv = (const float*)d_in[1];
    const float* w_out = (const float*)d_in[2];
    const float* b_out = (const float*)d_in[3];
    const float* w1    = (const float*)d_in[4];
    const float* wv    = (const float*)d_in[5];
    const float* w2    = (const float*)d_in[6];
    const float* ln1g  = (const float*)d_in[7];
    const float* ln1b  = (const float*)d_in[8];
    const float* ln2g  = (const float*)d_in[9];
    const float* ln2b  = (const float*)d_in[10];
    float* out = (float*)d_out;

    const int GSM = 4 * 128 * LD64 * 2;   // 73728 B (2-stage; 2 CTAs/SM)
    cudaFuncSetAttribute(k_gemm<256, 0>,  cudaFuncAttributeMaxDynamicSharedMemorySize, GSM);
    cudaFuncSetAttribute(k_gemm<256, 1>,  cudaFuncAttributeMaxDynamicSharedMemorySize, GSM);
    cudaFuncSetAttribute(k_gemm<1024, 2>, cudaFuncAttributeMaxDynamicSharedMemorySize, GSM);
    cudaFuncSetAttribute(k_ffn1,          cudaFuncAttributeMaxDynamicSharedMemorySize, GSM);

    k_cvt_all      <<<(CVT_TOT + 255) / 256, 256>>>(x, w_qkv, w_out, w1, wv, w2);
    k_gemm<256, 0> <<<dim3(3 * DD / 128, TT / 128), 256, GSM>>>(nullptr);  // QKV
    k_fattn        <<<dim3(NN / 256, HH, BB), 256>>>();                    // attention
    k_gemm<256, 1> <<<dim3(DD / 128, TT / 128), 256, GSM>>>(b_out);        // out-proj
    k_ln1          <<<TT / 8, 256>>>(x, ln1g, ln1b);
    k_ffn1         <<<dim3(DFF / 64, TT / 128), 256, GSM>>>();             // GEGLU up
    k_gemm<1024, 2><<<dim3(DD / 128, TT / 128), 256, GSM>>>(nullptr);      // FFN down
    k_ln2          <<<TT / 8, 256>>>(ln2g, ln2b, out);
}

// round 16
// speedup vs baseline: 1.0299x; 1.0299x over previous
#include <cuda_runtime.h>
#include <cuda_bf16.h>
#include <math.h>
#include <stdint.h>

#define BB   8
#define NN   2048
#define DD   256
#define HH   8
#define HD   32
#define DFF  1024
#define TT   (BB*NN)
#define LDT  40              // attention smem row stride (32 data + 8 pad)
#define VLD  136             // V^T smem row stride (128 data + 8 pad)
#define LD64 72              // GEMM smem row stride (64 data + 8 pad)
#define QSC  (0.17677669529663687f * 1.4426950408889634f)   // 1/sqrt(32) * log2(e)

// ---------------- fp32 scratch ----------------
__device__ float g_y[TT*DD];
__device__ float g_x1[TT*DD];
__device__ float g_z[TT*DD];

// ---------------- bf16 scratch ----------------
__device__ __nv_bfloat16 xb[TT*DD];
__device__ __nv_bfloat16 qb[BB*HH*NN*HD];      // scaled by log2e/sqrt(HD)
__device__ __nv_bfloat16 kb[BB*HH*NN*HD];
__device__ __nv_bfloat16 vtb[BB*HH*HD*NN];     // V transposed: [B,H,HD,N]
__device__ __nv_bfloat16 ob[TT*DD];
__device__ __nv_bfloat16 yb[TT*DD];
__device__ __nv_bfloat16 fb[TT*DFF];
__device__ __nv_bfloat16 wqkvb[3*DD*DD];
__device__ __nv_bfloat16 woutb[DD*DD];
__device__ __nv_bfloat16 w1b[DFF*DD];
__device__ __nv_bfloat16 wvb[DFF*DD];
__device__ __nv_bfloat16 w2b[DD*DFF];

// ---------------- helpers ----------------
__device__ __forceinline__ uint32_t sm_u32(const void* p) {
    uint32_t a;
    asm("{ .reg .u64 t; cvta.to.shared.u64 t, %1; cvt.u32.u64 %0, t; }" : "=r"(a) : "l"(p));
    return a;
}
__device__ __forceinline__ void cpa16(uint32_t dst, const void* src) {
    asm volatile("cp.async.cg.shared.global [%0], [%1], 16;" :: "r"(dst), "l"(src));
}
__device__ __forceinline__ void cpa_commit() {
    asm volatile("cp.async.commit_group;" ::: "memory");
}
template<int N>
__device__ __forceinline__ void cpa_wait() {
    asm volatile("cp.async.wait_group %0;" :: "n"(N) : "memory");
}
__device__ __forceinline__ void ldm_x4(uint32_t* r, uint32_t addr) {
    asm volatile("ldmatrix.sync.aligned.m8n8.x4.shared.b16 {%0,%1,%2,%3}, [%4];"
                 : "=r"(r[0]), "=r"(r[1]), "=r"(r[2]), "=r"(r[3]) : "r"(addr));
}
__device__ __forceinline__ void mma_bf16(float* d, const uint32_t* a, const uint32_t* b) {
    asm volatile("mma.sync.aligned.m16n8k16.row.col.f32.bf16.bf16.f32 "
                 "{%0,%1,%2,%3}, {%4,%5,%6,%7}, {%8,%9}, {%0,%1,%2,%3};"
                 : "+f"(d[0]), "+f"(d[1]), "+f"(d[2]), "+f"(d[3])
                 : "r"(a[0]), "r"(a[1]), "r"(a[2]), "r"(a[3]), "r"(b[0]), "r"(b[1]));
}
__device__ __forceinline__ float ex2f(float x) {
    float y;
    asm("ex2.approx.f32 %0, %1;" : "=f"(y) : "f"(x));
    return y;
}
__device__ __forceinline__ uint32_t packbf(float a, float b) {
    __nv_bfloat162 t = __floats2bfloat162_rn(a, b);
    return *reinterpret_cast<uint32_t*>(&t);
}
__device__ __forceinline__ float gelu_f(float x) {
    return 0.5f * x * (1.0f + erff(x * 0.70710678118654752f));
}

// Async-load an R x 64 bf16 tile (row-major, ldk elems) into smem with LD64 stride.
template<int R>
__device__ __forceinline__ void ld_tile64(const __nv_bfloat16* __restrict__ src,
                                          size_t rowbase, int ldk,
                                          uint32_t smbase, int tid) {
    #pragma unroll
    for (int i = 0; i < R * 8 / 256; ++i) {
        int s = tid + i * 256;
        int r = s >> 3, cs = s & 7;
        cpa16(smbase + (r * LD64 + cs * 8) * 2,
              src + rowbase + (size_t)r * ldk + cs * 8);
    }
}

// ---------------- bf16 HMMA GEMM (BK=64, 2-stage pipeline, paired-x4 B loads) ----------------
// Block 128x128, 8 warps (2 M x 4 N), warp tile 64x32.
// EPI: 0 = QKV scatter, 1 = outproj(+bias), 2 = ffn2 -> g_z
template<int KTOT, int EPI>
__global__ void __launch_bounds__(256, 2) k_gemm(const float* __restrict__ bias) {
    extern __shared__ __nv_bfloat16 dsm[];
    constexpr int TSZ = 128 * LD64;
    const int tid = threadIdx.x, wid = tid >> 5, lane = tid & 31;
    const int wm = wid >> 2, wn = wid & 3;
    const int m0 = blockIdx.y * 128, n0 = blockIdx.x * 128;

    const __nv_bfloat16 *pA, *pB;
    if constexpr (EPI == 0)      { pA = xb; pB = wqkvb; }
    else if constexpr (EPI == 1) { pA = ob; pB = woutb; }
    else                         { pA = fb; pB = w2b;   }

    float acc[4][4][4] = {};
    uint32_t sA[2], sB[2];
    #pragma unroll
    for (int s = 0; s < 2; ++s) {
        sA[s] = sm_u32(dsm + s * TSZ);
        sB[s] = sm_u32(dsm + (2 + s) * TSZ);
    }
    const int a_row = wm * 64 + (lane & 15);
    const int a_k   = (lane >> 4) * 8;
    const int b_row4 = wn * 32 + ((lane >> 4) << 3) + (lane & 7);
    const int b_k    = ((lane >> 3) & 1) * 8;

    constexpr int NCH = KTOT / 64;
    ld_tile64<128>(pA, (size_t)m0 * KTOT, KTOT, sA[0], tid);
    ld_tile64<128>(pB, (size_t)n0 * KTOT, KTOT, sB[0], tid);
    cpa_commit();

    for (int c = 0; c < NCH; ++c) {
        if (c + 1 < NCH) {
            const int nb = (c + 1) & 1;
            ld_tile64<128>(pA, (size_t)m0 * KTOT + (c + 1) * 64, KTOT, sA[nb], tid);
            ld_tile64<128>(pB, (size_t)n0 * KTOT + (c + 1) * 64, KTOT, sB[nb], tid);
            cpa_commit();
            cpa_wait<1>();
        } else {
            cpa_wait<0>();
        }
        __syncthreads();
        const uint32_t bA = sA[c & 1], bB = sB[c & 1];
        #pragma unroll
        for (int ks = 0; ks < 64; ks += 16) {
            uint32_t fA[4][4], fB[2][4];
            #pragma unroll
            for (int mi = 0; mi < 4; ++mi)
                ldm_x4(fA[mi], bA + ((a_row + mi * 16) * LD64 + ks + a_k) * 2);
            #pragma unroll
            for (int p = 0; p < 2; ++p)
                ldm_x4(fB[p], bB + ((b_row4 + p * 16) * LD64 + ks + b_k) * 2);
            #pragma unroll
            for (int mi = 0; mi < 4; ++mi)
                #pragma unroll
                for (int ni = 0; ni < 4; ++ni)
                    mma_bf16(acc[mi][ni], fA[mi], &fB[ni >> 1][(ni & 1) * 2]);
        }
        __syncthreads();
    }

    #pragma unroll
    for (int mi = 0; mi < 4; ++mi) {
        #pragma unroll
        for (int ni = 0; ni < 4; ++ni) {
            const int r = m0 + wm * 64 + mi * 16 + (lane >> 2);
            const int cc = n0 + wn * 32 + ni * 8 + (lane & 3) * 2;
            #pragma unroll
            for (int half = 0; half < 2; ++half) {
                const int m = r + half * 8;
                const float v0 = acc[mi][ni][half * 2 + 0];
                const float v1 = acc[mi][ni][half * 2 + 1];
                if constexpr (EPI == 0) {
                    const int part = cc >> 8, hh = (cc >> 5) & 7, d = cc & 31;
                    const int b = m >> 11, nn = m & 2047;
                    const size_t bh = (size_t)(b * HH + hh);
                    if (part == 0) {
                        *reinterpret_cast<__nv_bfloat162*>(qb + (bh * NN + nn) * HD + d)
                            = __floats2bfloat162_rn(v0 * QSC, v1 * QSC);
                    } else if (part == 1) {
                        *reinterpret_cast<__nv_bfloat162*>(kb + (bh * NN + nn) * HD + d)
                            = __floats2bfloat162_rn(v0, v1);
                    } else {
                        vtb[(bh * HD + d)     * NN + nn] = __float2bfloat16(v0);
                        vtb[(bh * HD + d + 1) * NN + nn] = __float2bfloat16(v1);
                    }
                } else if constexpr (EPI == 1) {
                    const float y0 = v0 + bias[cc], y1 = v1 + bias[cc + 1];
                    *reinterpret_cast<float2*>(g_y + (size_t)m * DD + cc) = make_float2(y0, y1);
                    *reinterpret_cast<__nv_bfloat162*>(yb + (size_t)m * DD + cc)
                        = __floats2bfloat162_rn(y0, y1);
                } else {
                    *reinterpret_cast<float2*>(g_z + (size_t)m * DD + cc) = make_float2(v0, v1);
                }
            }
        }
    }
}

// ---------------- dual-B GEMM (GEGLU up, BK=64, paired-x4 B loads) ----------------
// Block 128x64, 8 warps (4 M x 2 N), warp tile 32x32.
__global__ void __launch_bounds__(256, 2) k_ffn1() {
    extern __shared__ __nv_bfloat16 dsm[];
    constexpr int ASZ = 128 * LD64, BSZ = 64 * LD64;
    const int tid = threadIdx.x, wid = tid >> 5, lane = tid & 31;
    const int wm = wid >> 1, wn = wid & 1;
    const int m0 = blockIdx.y * 128, n0 = blockIdx.x * 64;

    float acc1[2][4][4] = {}, acc2[2][4][4] = {};
    uint32_t sA[2], sB1[2], sB2[2];
    #pragma unroll
    for (int s = 0; s < 2; ++s) {
        sA[s]  = sm_u32(dsm + s * ASZ);
        sB1[s] = sm_u32(dsm + 2 * ASZ + s * BSZ);
        sB2[s] = sm_u32(dsm + 2 * ASZ + 2 * BSZ + s * BSZ);
    }
    const int a_row = wm * 32 + (lane & 15);
    const int a_k   = (lane >> 4) * 8;
    const int b_row4 = wn * 32 + ((lane >> 4) << 3) + (lane & 7);
    const int b_k    = ((lane >> 3) & 1) * 8;

    constexpr int NCH = DD / 64;
    auto ldchunk = [&](int c, int buf) {
        ld_tile64<128>(yb,  (size_t)m0 * DD + c * 64, DD, sA[buf],  tid);
        ld_tile64<64>(w1b,  (size_t)n0 * DD + c * 64, DD, sB1[buf], tid);
        ld_tile64<64>(wvb,  (size_t)n0 * DD + c * 64, DD, sB2[buf], tid);
        cpa_commit();
    };
    ldchunk(0, 0);

    for (int c = 0; c < NCH; ++c) {
        if (c + 1 < NCH) {
            ldchunk(c + 1, (c + 1) & 1);
            cpa_wait<1>();
        } else {
            cpa_wait<0>();
        }
        __syncthreads();
        const uint32_t bA = sA[c & 1], bB1 = sB1[c & 1], bB2 = sB2[c & 1];
        #pragma unroll
        for (int ks = 0; ks < 64; ks += 16) {
            uint32_t fA[2][4], f1[2][4], f2[2][4];
            #pragma unroll
            for (int mi = 0; mi < 2; ++mi)
                ldm_x4(fA[mi], bA + ((a_row + mi * 16) * LD64 + ks + a_k) * 2);
            #pragma unroll
            for (int p = 0; p < 2; ++p) {
                const uint32_t off = ((b_row4 + p * 16) * LD64 + ks + b_k) * 2;
                ldm_x4(f1[p], bB1 + off);
                ldm_x4(f2[p], bB2 + off);
            }
            #pragma unroll
            for (int mi = 0; mi < 2; ++mi)
                #pragma unroll
                for (int ni = 0; ni < 4; ++ni) {
                    mma_bf16(acc1[mi][ni], fA[mi], &f1[ni >> 1][(ni & 1) * 2]);
                    mma_bf16(acc2[mi][ni], fA[mi], &f2[ni >> 1][(ni & 1) * 2]);
                }
        }
        __syncthreads();
    }

    #pragma unroll
    for (int mi = 0; mi < 2; ++mi)
        #pragma unroll
        for (int ni = 0; ni < 4; ++ni) {
            const int r = m0 + wm * 32 + mi * 16 + (lane >> 2);
            const int cc = n0 + wn * 32 + ni * 8 + (lane & 3) * 2;
            #pragma unroll
            for (int half = 0; half < 2; ++half) {
                const int m = r + half * 8;
                const float f0 = gelu_f(acc1[mi][ni][half * 2]) * acc2[mi][ni][half * 2];
                const float f1 = gelu_f(acc1[mi][ni][half * 2 + 1]) * acc2[mi][ni][half * 2 + 1];
                *reinterpret_cast<__nv_bfloat162*>(fb + (size_t)m * DFF + cc)
                    = __floats2bfloat162_rn(f0, f1);
            }
        }
}

// ---------------- HMMA flash attention (fused S->exp->PV strips; 3 CTAs/SM) ----------------
__global__ void __launch_bounds__(256, 3) k_fattn() {
    __shared__ __nv_bfloat16 Qs[128 * LDT], Ks[2][128 * LDT], Vts[2][32 * VLD];
    const int tid = threadIdx.x, w = tid >> 5, lane = tid & 31;
    const int b = blockIdx.z, h = blockIdx.y, q0 = blockIdx.x * 128;
    const size_t bh = (size_t)(b * HH + h);
    const __nv_bfloat16* Qg = qb + bh * NN * HD + (size_t)q0 * HD;
    const __nv_bfloat16* Kg = kb + bh * NN * HD;
    const __nv_bfloat16* Vg = vtb + bh * HD * NN;

    #pragma unroll
    for (int i = 0; i < 2; ++i) {
        int s = tid + i * 256;
        int r = s >> 2, cs = s & 3;
        float4 v = *reinterpret_cast<const float4*>(Qg + (size_t)r * HD + cs * 8);
        *reinterpret_cast<float4*>(&Qs[r * LDT + cs * 8]) = v;
    }
    const uint32_t sQ = sm_u32(Qs);
    const uint32_t sK[2] = { sm_u32(Ks[0]),  sm_u32(Ks[1])  };
    const uint32_t sV[2] = { sm_u32(Vts[0]), sm_u32(Vts[1]) };

    auto ldkv = [&](int j0, int buf) {
        #pragma unroll
        for (int i = 0; i < 2; ++i) {
            int s = tid + i * 256;
            int r = s >> 2, cs = s & 3;
            cpa16(sK[buf] + (r * LDT + cs * 8) * 2, Kg + (size_t)(j0 + r) * HD + cs * 8);
        }
        #pragma unroll
        for (int i = 0; i < 2; ++i) {
            int s = tid + i * 256;
            int r = s >> 4, cs = s & 15;
            cpa16(sV[buf] + (r * VLD + cs * 8) * 2, Vg + (size_t)r * NN + j0 + cs * 8);
        }
        cpa_commit();
    };
    ldkv(0, 0);

    __syncthreads();
    uint32_t qA[2][4];
    {
        const int arow = w * 16 + (lane & 15);
        const int ak   = (lane >> 4) * 8;
        ldm_x4(qA[0], sQ + (arow * LDT + ak) * 2);
        ldm_x4(qA[1], sQ + (arow * LDT + 16 + ak) * 2);
    }

    float l0 = 0.f, l1 = 0.f;
    float Of[4][4] = {};
    const int b_row4 = ((lane >> 4) << 3) + (lane & 7);
    const int b_k    = ((lane >> 3) & 1) * 8;

    for (int j0 = 0; j0 < NN; j0 += 128) {
        cpa_wait<0>();
        __syncthreads();
        if (j0 + 128 < NN) ldkv(j0 + 128, ((j0 >> 7) + 1) & 1);
        const int bf = (j0 >> 7) & 1;

        // Per 16-key strip p: S (QK) -> exp -> PV, only 8 live score regs.
        #pragma unroll
        for (int p = 0; p < 8; ++p) {
            float sf[2][4] = {};
            #pragma unroll
            for (int ks = 0; ks < 2; ++ks) {
                uint32_t bb[4];
                ldm_x4(bb, sK[bf] + ((p * 16 + b_row4) * LDT + ks * 16 + b_k) * 2);
                mma_bf16(sf[0], qA[ks], &bb[0]);
                mma_bf16(sf[1], qA[ks], &bb[2]);
            }
            const float p00 = ex2f(sf[0][0]);
            const float p01 = ex2f(sf[0][1]);
            const float p10 = ex2f(sf[0][2]);
            const float p11 = ex2f(sf[0][3]);
            const float p20 = ex2f(sf[1][0]);
            const float p21 = ex2f(sf[1][1]);
            const float p30 = ex2f(sf[1][2]);
            const float p31 = ex2f(sf[1][3]);
            l0 += p00 + p01 + p20 + p21;
            l1 += p10 + p11 + p30 + p31;
            uint32_t pa[4];
            pa[0] = packbf(p00, p01);
            pa[1] = packbf(p10, p11);
            pa[2] = packbf(p20, p21);
            pa[3] = packbf(p30, p31);
            #pragma unroll
            for (int pp = 0; pp < 2; ++pp) {
                uint32_t vv[4];
                ldm_x4(vv, sV[bf] + ((pp * 16 + b_row4) * VLD + p * 16 + b_k) * 2);
                mma_bf16(Of[2 * pp],     pa, &vv[0]);
                mma_bf16(Of[2 * pp + 1], pa, &vv[2]);
            }
        }
    }

    l0 += __shfl_xor_sync(0xffffffffu, l0, 1);
    l0 += __shfl_xor_sync(0xffffffffu, l0, 2);
    l1 += __shfl_xor_sync(0xffffffffu, l1, 1);
    l1 += __shfl_xor_sync(0xffffffffu, l1, 2);

    const float i0 = 1.0f / l0, i1 = 1.0f / l1;
    const int t0 = b * NN + q0 + w * 16 + (lane >> 2);
    const int c2 = (lane & 3) * 2;
    #pragma unroll
    for (int nf = 0; nf < 4; ++nf) {
        const int d = h * HD + nf * 8 + c2;
        *reinterpret_cast<__nv_bfloat162*>(ob + (size_t)t0 * DD + d)
            = __floats2bfloat162_rn(Of[nf][0] * i0, Of[nf][1] * i0);
        *reinterpret_cast<__nv_bfloat162*>(ob + (size_t)(t0 + 8) * DD + d)
            = __floats2bfloat162_rn(Of[nf][2] * i1, Of[nf][3] * i1);
    }
}

// ---------------- merged fp32 -> bf16 conversion ----------------
#define C_X   (TT*DD/4)
#define C_QKV (3*DD*DD/4)
#define C_OUT (DD*DD/4)
#define C_W1  (DFF*DD/4)
#define CVT_TOT (C_X + C_QKV + C_OUT + 3*C_W1)
__global__ void __launch_bounds__(256) k_cvt_all(const float* __restrict__ x,
                                                 const float* __restrict__ wq,
                                                 const float* __restrict__ wo,
                                                 const float* __restrict__ w1,
                                                 const float* __restrict__ wv,
                                                 const float* __restrict__ w2) {
    int i = blockIdx.x * 256 + threadIdx.x;
    if (i >= CVT_TOT) return;
    const float* s;
    __nv_bfloat16* d;
    int o = i;
    if (o < C_X)                      { s = x;  d = xb;    }
    else if ((o -= C_X)   < C_QKV)    { s = wq; d = wqkvb; }
    else if ((o -= C_QKV) < C_OUT)    { s = wo; d = woutb; }
    else if ((o -= C_OUT) < C_W1)     { s = w1; d = w1b;   }
    else if ((o -= C_W1)  < C_W1)     { s = wv; d = wvb;   }
    else                              { o -= C_W1; s = w2; d = w2b; }
    float4 v = reinterpret_cast<const float4*>(s)[o];
    reinterpret_cast<__nv_bfloat162*>(d)[2 * o]     = __floats2bfloat162_rn(v.x, v.y);
    reinterpret_cast<__nv_bfloat162*>(d)[2 * o + 1] = __floats2bfloat162_rn(v.z, v.w);
}

// ---------------- warp-per-row Add + LayerNorm ----------------
__device__ __forceinline__ void ln_row(const float* __restrict__ pa,
                                       const float* __restrict__ pb,
                                       const float* __restrict__ g,
                                       const float* __restrict__ beta,
                                       float* __restrict__ out, int lane) {
    float vals[8];
    float s = 0.f, s2 = 0.f;
    #pragma unroll
    for (int i = 0; i < 8; ++i) {
        float v = pa[lane + i * 32] + pb[lane + i * 32];
        vals[i] = v; s += v; s2 += v * v;
    }
    #pragma unroll
    for (int off = 16; off >= 1; off >>= 1) {
        s  += __shfl_xor_sync(0xffffffffu, s, off);
        s2 += __shfl_xor_sync(0xffffffffu, s2, off);
    }
    const float mean = s * (1.0f / DD);
    const float var = s2 * (1.0f / DD) - mean * mean;
    const float inv = rsqrtf(var + 1e-5f);
    #pragma unroll
    for (int i = 0; i < 8; ++i) {
        const int c = lane + i * 32;
        out[c] = (vals[i] - mean) * inv * g[c] + beta[c];
    }
}

__global__ void __launch_bounds__(256) k_ln1(const float* __restrict__ x,
                                             const float* __restrict__ g,
                                             const float* __restrict__ beta) {
    const int row = blockIdx.x * 8 + (threadIdx.x >> 5);
    const int lane = threadIdx.x & 31;
    ln_row(g_y + (size_t)row * DD, x + (size_t)row * DD, g, beta,
           g_x1 + (size_t)row * DD, lane);
}

__global__ void __launch_bounds__(256) k_ln2(const float* __restrict__ g,
                                             const float* __restrict__ beta,
                                             float* __restrict__ out) {
    const int row = blockIdx.x * 8 + (threadIdx.x >> 5);
    const int lane = threadIdx.x & 31;
    ln_row(g_z + (size_t)row * DD, g_x1 + (size_t)row * DD, g, beta,
           out + (size_t)row * DD, lane);
}

// ---------------- launch ----------------
extern "C" void kernel_launch(void* const* d_in, const int* in_sizes, int n_in,
                              void* d_out, int out_size) {
    const float* x     = (const float*)d_in[0];
    const float* w_qkv = (const float*)d_in[1];
    const float* w_out = (const float*)d_in[2];
    const float* b_out = (const float*)d_in[3];
    const float* w1    = (const float*)d_in[4];
    const float* wv    = (const float*)d_in[5];
    const float* w2    = (const float*)d_in[6];
    const float* ln1g  = (const float*)d_in[7];
    const float* ln1b  = (const float*)d_in[8];
    const float* ln2g  = (const float*)d_in[9];
    const float* ln2b  = (const float*)d_in[10];
    float* out = (float*)d_out;

    const int GSM = 4 * 128 * LD64 * 2;   // 73728 B (2-stage; 2 CTAs/SM)
    cudaFuncSetAttribute(k_gemm<256, 0>,  cudaFuncAttributeMaxDynamicSharedMemorySize, GSM);
    cudaFuncSetAttribute(k_gemm<256, 1>,  cudaFuncAttributeMaxDynamicSharedMemorySize, GSM);
    cudaFuncSetAttribute(k_gemm<1024, 2>, cudaFuncAttributeMaxDynamicSharedMemorySize, GSM);
    cudaFuncSetAttribute(k_ffn1,          cudaFuncAttributeMaxDynamicSharedMemorySize, GSM);

    k_cvt_all      <<<(CVT_TOT + 255) / 256, 256>>>(x, w_qkv, w_out, w1, wv, w2);
    k_gemm<256, 0> <<<dim3(3 * DD / 128, TT / 128), 256, GSM>>>(nullptr);  // QKV
    k_fattn        <<<dim3(NN / 128, HH, BB), 256>>>();                    // attention
    k_gemm<256, 1> <<<dim3(DD / 128, TT / 128), 256, GSM>>>(b_out);        // out-proj
    k_ln1          <<<TT / 8, 256>>>(x, ln1g, ln1b);
    k_ffn1         <<<dim3(DFF / 64, TT / 128), 256, GSM>>>();             // GEGLU up
    k_gemm<1024, 2><<<dim3(DD / 128, TT / 128), 256, GSM>>>(nullptr);      // FFN down
    k_ln2          <<<TT / 8, 256>>>(ln2g, ln2b, out);
}

// round 17
// speedup vs baseline: 1.0440x; 1.0137x over previous
#include <cuda_runtime.h>
#include <cuda_bf16.h>
#include <math.h>
#include <stdint.h>

#define BB   8
#define NN   2048
#define DD   256
#define HH   8
#define HD   32
#define DFF  1024
#define TT   (BB*NN)
#define LDT  40              // attention smem row stride (32 data + 8 pad)
#define VLD  136             // V^T smem row stride (128 data + 8 pad)
#define LD64 72              // GEMM smem row stride (64 data + 8 pad)
#define QSC  (0.17677669529663687f * 1.4426950408889634f)   // 1/sqrt(32) * log2(e)

// ---------------- fp32 scratch ----------------
__device__ float g_x1[TT*DD];

// ---------------- bf16 scratch ----------------
__device__ __nv_bfloat16 xb[TT*DD];
__device__ __nv_bfloat16 qb[BB*HH*NN*HD];      // scaled by log2e/sqrt(HD)
__device__ __nv_bfloat16 kb[BB*HH*NN*HD];
__device__ __nv_bfloat16 vtb[BB*HH*HD*NN];     // V transposed: [B,H,HD,N]
__device__ __nv_bfloat16 ob[TT*DD];
__device__ __nv_bfloat16 yb[TT*DD];            // y = out-proj + bias (bf16; feeds FFN and LN1)
__device__ __nv_bfloat16 zb[TT*DD];            // z = ff@w2^T (bf16; feeds LN2)
__device__ __nv_bfloat16 fb[TT*DFF];
__device__ __nv_bfloat16 wqkvb[3*DD*DD];
__device__ __nv_bfloat16 woutb[DD*DD];
__device__ __nv_bfloat16 w1b[DFF*DD];
__device__ __nv_bfloat16 wvb[DFF*DD];
__device__ __nv_bfloat16 w2b[DD*DFF];

// ---------------- helpers ----------------
__device__ __forceinline__ uint32_t sm_u32(const void* p) {
    uint32_t a;
    asm("{ .reg .u64 t; cvta.to.shared.u64 t, %1; cvt.u32.u64 %0, t; }" : "=r"(a) : "l"(p));
    return a;
}
__device__ __forceinline__ void cpa16(uint32_t dst, const void* src) {
    asm volatile("cp.async.cg.shared.global [%0], [%1], 16;" :: "r"(dst), "l"(src));
}
__device__ __forceinline__ void cpa_commit() {
    asm volatile("cp.async.commit_group;" ::: "memory");
}
template<int N>
__device__ __forceinline__ void cpa_wait() {
    asm volatile("cp.async.wait_group %0;" :: "n"(N) : "memory");
}
__device__ __forceinline__ void ldm_x4(uint32_t* r, uint32_t addr) {
    asm volatile("ldmatrix.sync.aligned.m8n8.x4.shared.b16 {%0,%1,%2,%3}, [%4];"
                 : "=r"(r[0]), "=r"(r[1]), "=r"(r[2]), "=r"(r[3]) : "r"(addr));
}
__device__ __forceinline__ void mma_bf16(float* d, const uint32_t* a, const uint32_t* b) {
    asm volatile("mma.sync.aligned.m16n8k16.row.col.f32.bf16.bf16.f32 "
                 "{%0,%1,%2,%3}, {%4,%5,%6,%7}, {%8,%9}, {%0,%1,%2,%3};"
                 : "+f"(d[0]), "+f"(d[1]), "+f"(d[2]), "+f"(d[3])
                 : "r"(a[0]), "r"(a[1]), "r"(a[2]), "r"(a[3]), "r"(b[0]), "r"(b[1]));
}
__device__ __forceinline__ float ex2f(float x) {
    float y;
    asm("ex2.approx.f32 %0, %1;" : "=f"(y) : "f"(x));
    return y;
}
__device__ __forceinline__ uint32_t packbf(float a, float b) {
    __nv_bfloat162 t = __floats2bfloat162_rn(a, b);
    return *reinterpret_cast<uint32_t*>(&t);
}
__device__ __forceinline__ float gelu_f(float x) {
    return 0.5f * x * (1.0f + erff(x * 0.70710678118654752f));
}

// Async-load an R x 64 bf16 tile (row-major, ldk elems) into smem with LD64 stride.
template<int R>
__device__ __forceinline__ void ld_tile64(const __nv_bfloat16* __restrict__ src,
                                          size_t rowbase, int ldk,
                                          uint32_t smbase, int tid) {
    #pragma unroll
    for (int i = 0; i < R * 8 / 256; ++i) {
        int s = tid + i * 256;
        int r = s >> 3, cs = s & 7;
        cpa16(smbase + (r * LD64 + cs * 8) * 2,
              src + rowbase + (size_t)r * ldk + cs * 8);
    }
}

// ---------------- bf16 HMMA GEMM (BK=64, 2-stage pipeline, paired-x4 B loads) ----------------
// Block 128x128, 8 warps (2 M x 4 N), warp tile 64x32.
// EPI: 0 = QKV scatter, 1 = outproj(+bias) -> yb, 2 = ffn2 -> zb
template<int KTOT, int EPI>
__global__ void __launch_bounds__(256, 2) k_gemm(const float* __restrict__ bias) {
    extern __shared__ __nv_bfloat16 dsm[];
    constexpr int TSZ = 128 * LD64;
    const int tid = threadIdx.x, wid = tid >> 5, lane = tid & 31;
    const int wm = wid >> 2, wn = wid & 3;
    const int m0 = blockIdx.y * 128, n0 = blockIdx.x * 128;

    const __nv_bfloat16 *pA, *pB;
    if constexpr (EPI == 0)      { pA = xb; pB = wqkvb; }
    else if constexpr (EPI == 1) { pA = ob; pB = woutb; }
    else                         { pA = fb; pB = w2b;   }

    float acc[4][4][4] = {};
    uint32_t sA[2], sB[2];
    #pragma unroll
    for (int s = 0; s < 2; ++s) {
        sA[s] = sm_u32(dsm + s * TSZ);
        sB[s] = sm_u32(dsm + (2 + s) * TSZ);
    }
    const int a_row = wm * 64 + (lane & 15);
    const int a_k   = (lane >> 4) * 8;
    const int b_row4 = wn * 32 + ((lane >> 4) << 3) + (lane & 7);
    const int b_k    = ((lane >> 3) & 1) * 8;

    constexpr int NCH = KTOT / 64;
    ld_tile64<128>(pA, (size_t)m0 * KTOT, KTOT, sA[0], tid);
    ld_tile64<128>(pB, (size_t)n0 * KTOT, KTOT, sB[0], tid);
    cpa_commit();

    for (int c = 0; c < NCH; ++c) {
        if (c + 1 < NCH) {
            const int nb = (c + 1) & 1;
            ld_tile64<128>(pA, (size_t)m0 * KTOT + (c + 1) * 64, KTOT, sA[nb], tid);
            ld_tile64<128>(pB, (size_t)n0 * KTOT + (c + 1) * 64, KTOT, sB[nb], tid);
            cpa_commit();
            cpa_wait<1>();
        } else {
            cpa_wait<0>();
        }
        __syncthreads();
        const uint32_t bA = sA[c & 1], bB = sB[c & 1];
        #pragma unroll
        for (int ks = 0; ks < 64; ks += 16) {
            uint32_t fA[4][4], fB[2][4];
            #pragma unroll
            for (int mi = 0; mi < 4; ++mi)
                ldm_x4(fA[mi], bA + ((a_row + mi * 16) * LD64 + ks + a_k) * 2);
            #pragma unroll
            for (int p = 0; p < 2; ++p)
                ldm_x4(fB[p], bB + ((b_row4 + p * 16) * LD64 + ks + b_k) * 2);
            #pragma unroll
            for (int mi = 0; mi < 4; ++mi)
                #pragma unroll
                for (int ni = 0; ni < 4; ++ni)
                    mma_bf16(acc[mi][ni], fA[mi], &fB[ni >> 1][(ni & 1) * 2]);
        }
        __syncthreads();
    }

    #pragma unroll
    for (int mi = 0; mi < 4; ++mi) {
        #pragma unroll
        for (int ni = 0; ni < 4; ++ni) {
            const int r = m0 + wm * 64 + mi * 16 + (lane >> 2);
            const int cc = n0 + wn * 32 + ni * 8 + (lane & 3) * 2;
            #pragma unroll
            for (int half = 0; half < 2; ++half) {
                const int m = r + half * 8;
                const float v0 = acc[mi][ni][half * 2 + 0];
                const float v1 = acc[mi][ni][half * 2 + 1];
                if constexpr (EPI == 0) {
                    const int part = cc >> 8, hh = (cc >> 5) & 7, d = cc & 31;
                    const int b = m >> 11, nn = m & 2047;
                    const size_t bh = (size_t)(b * HH + hh);
                    if (part == 0) {
                        *reinterpret_cast<__nv_bfloat162*>(qb + (bh * NN + nn) * HD + d)
                            = __floats2bfloat162_rn(v0 * QSC, v1 * QSC);
                    } else if (part == 1) {
                        *reinterpret_cast<__nv_bfloat162*>(kb + (bh * NN + nn) * HD + d)
                            = __floats2bfloat162_rn(v0, v1);
                    } else {
                        vtb[(bh * HD + d)     * NN + nn] = __float2bfloat16(v0);
                        vtb[(bh * HD + d + 1) * NN + nn] = __float2bfloat16(v1);
                    }
                } else if constexpr (EPI == 1) {
                    *reinterpret_cast<__nv_bfloat162*>(yb + (size_t)m * DD + cc)
                        = __floats2bfloat162_rn(v0 + bias[cc], v1 + bias[cc + 1]);
                } else {
                    *reinterpret_cast<__nv_bfloat162*>(zb + (size_t)m * DD + cc)
                        = __floats2bfloat162_rn(v0, v1);
                }
            }
        }
    }
}

// ---------------- dual-B GEMM (GEGLU up, BK=64, paired-x4 B loads) ----------------
// Block 128x64, 8 warps (4 M x 2 N), warp tile 32x32.
__global__ void __launch_bounds__(256, 2) k_ffn1() {
    extern __shared__ __nv_bfloat16 dsm[];
    constexpr int ASZ = 128 * LD64, BSZ = 64 * LD64;
    const int tid = threadIdx.x, wid = tid >> 5, lane = tid & 31;
    const int wm = wid >> 1, wn = wid & 1;
    const int m0 = blockIdx.y * 128, n0 = blockIdx.x * 64;

    float acc1[2][4][4] = {}, acc2[2][4][4] = {};
    uint32_t sA[2], sB1[2], sB2[2];
    #pragma unroll
    for (int s = 0; s < 2; ++s) {
        sA[s]  = sm_u32(dsm + s * ASZ);
        sB1[s] = sm_u32(dsm + 2 * ASZ + s * BSZ);
        sB2[s] = sm_u32(dsm + 2 * ASZ + 2 * BSZ + s * BSZ);
    }
    const int a_row = wm * 32 + (lane & 15);
    const int a_k   = (lane >> 4) * 8;
    const int b_row4 = wn * 32 + ((lane >> 4) << 3) + (lane & 7);
    const int b_k    = ((lane >> 3) & 1) * 8;

    constexpr int NCH = DD / 64;
    auto ldchunk = [&](int c, int buf) {
        ld_tile64<128>(yb,  (size_t)m0 * DD + c * 64, DD, sA[buf],  tid);
        ld_tile64<64>(w1b,  (size_t)n0 * DD + c * 64, DD, sB1[buf], tid);
        ld_tile64<64>(wvb,  (size_t)n0 * DD + c * 64, DD, sB2[buf], tid);
        cpa_commit();
    };
    ldchunk(0, 0);

    for (int c = 0; c < NCH; ++c) {
        if (c + 1 < NCH) {
            ldchunk(c + 1, (c + 1) & 1);
            cpa_wait<1>();
        } else {
            cpa_wait<0>();
        }
        __syncthreads();
        const uint32_t bA = sA[c & 1], bB1 = sB1[c & 1], bB2 = sB2[c & 1];
        #pragma unroll
        for (int ks = 0; ks < 64; ks += 16) {
            uint32_t fA[2][4], f1[2][4], f2[2][4];
            #pragma unroll
            for (int mi = 0; mi < 2; ++mi)
                ldm_x4(fA[mi], bA + ((a_row + mi * 16) * LD64 + ks + a_k) * 2);
            #pragma unroll
            for (int p = 0; p < 2; ++p) {
                const uint32_t off = ((b_row4 + p * 16) * LD64 + ks + b_k) * 2;
                ldm_x4(f1[p], bB1 + off);
                ldm_x4(f2[p], bB2 + off);
            }
            #pragma unroll
            for (int mi = 0; mi < 2; ++mi)
                #pragma unroll
                for (int ni = 0; ni < 4; ++ni) {
                    mma_bf16(acc1[mi][ni], fA[mi], &f1[ni >> 1][(ni & 1) * 2]);
                    mma_bf16(acc2[mi][ni], fA[mi], &f2[ni >> 1][(ni & 1) * 2]);
                }
        }
        __syncthreads();
    }

    #pragma unroll
    for (int mi = 0; mi < 2; ++mi)
        #pragma unroll
        for (int ni = 0; ni < 4; ++ni) {
            const int r = m0 + wm * 32 + mi * 16 + (lane >> 2);
            const int cc = n0 + wn * 32 + ni * 8 + (lane & 3) * 2;
            #pragma unroll
            for (int half = 0; half < 2; ++half) {
                const int m = r + half * 8;
                const float f0 = gelu_f(acc1[mi][ni][half * 2]) * acc2[mi][ni][half * 2];
                const float f1 = gelu_f(acc1[mi][ni][half * 2 + 1]) * acc2[mi][ni][half * 2 + 1];
                *reinterpret_cast<__nv_bfloat162*>(fb + (size_t)m * DFF + cc)
                    = __floats2bfloat162_rn(f0, f1);
            }
        }
}

// ---------------- HMMA flash attention (fused S->exp->PV strips; 3 CTAs/SM) ----------------
__global__ void __launch_bounds__(256, 3) k_fattn() {
    __shared__ __nv_bfloat16 Qs[128 * LDT], Ks[2][128 * LDT], Vts[2][32 * VLD];
    const int tid = threadIdx.x, w = tid >> 5, lane = tid & 31;
    const int b = blockIdx.z, h = blockIdx.y, q0 = blockIdx.x * 128;
    const size_t bh = (size_t)(b * HH + h);
    const __nv_bfloat16* Qg = qb + bh * NN * HD + (size_t)q0 * HD;
    const __nv_bfloat16* Kg = kb + bh * NN * HD;
    const __nv_bfloat16* Vg = vtb + bh * HD * NN;

    #pragma unroll
    for (int i = 0; i < 2; ++i) {
        int s = tid + i * 256;
        int r = s >> 2, cs = s & 3;
        float4 v = *reinterpret_cast<const float4*>(Qg + (size_t)r * HD + cs * 8);
        *reinterpret_cast<float4*>(&Qs[r * LDT + cs * 8]) = v;
    }
    const uint32_t sQ = sm_u32(Qs);
    const uint32_t sK[2] = { sm_u32(Ks[0]),  sm_u32(Ks[1])  };
    const uint32_t sV[2] = { sm_u32(Vts[0]), sm_u32(Vts[1]) };

    auto ldkv = [&](int j0, int buf) {
        #pragma unroll
        for (int i = 0; i < 2; ++i) {
            int s = tid + i * 256;
            int r = s >> 2, cs = s & 3;
            cpa16(sK[buf] + (r * LDT + cs * 8) * 2, Kg + (size_t)(j0 + r) * HD + cs * 8);
        }
        #pragma unroll
        for (int i = 0; i < 2; ++i) {
            int s = tid + i * 256;
            int r = s >> 4, cs = s & 15;
            cpa16(sV[buf] + (r * VLD + cs * 8) * 2, Vg + (size_t)r * NN + j0 + cs * 8);
        }
        cpa_commit();
    };
    ldkv(0, 0);

    __syncthreads();
    uint32_t qA[2][4];
    {
        const int arow = w * 16 + (lane & 15);
        const int ak   = (lane >> 4) * 8;
        ldm_x4(qA[0], sQ + (arow * LDT + ak) * 2);
        ldm_x4(qA[1], sQ + (arow * LDT + 16 + ak) * 2);
    }

    float l0 = 0.f, l1 = 0.f;
    float Of[4][4] = {};
    const int b_row4 = ((lane >> 4) << 3) + (lane & 7);
    const int b_k    = ((lane >> 3) & 1) * 8;

    for (int j0 = 0; j0 < NN; j0 += 128) {
        cpa_wait<0>();
        __syncthreads();
        if (j0 + 128 < NN) ldkv(j0 + 128, ((j0 >> 7) + 1) & 1);
        const int bf = (j0 >> 7) & 1;

        // Per 16-key strip p: S (QK) -> exp -> PV, only 8 live score regs.
        #pragma unroll
        for (int p = 0; p < 8; ++p) {
            float sf[2][4] = {};
            #pragma unroll
            for (int ks = 0; ks < 2; ++ks) {
                uint32_t bb[4];
                ldm_x4(bb, sK[bf] + ((p * 16 + b_row4) * LDT + ks * 16 + b_k) * 2);
                mma_bf16(sf[0], qA[ks], &bb[0]);
                mma_bf16(sf[1], qA[ks], &bb[2]);
            }
            const float p00 = ex2f(sf[0][0]);
            const float p01 = ex2f(sf[0][1]);
            const float p10 = ex2f(sf[0][2]);
            const float p11 = ex2f(sf[0][3]);
            const float p20 = ex2f(sf[1][0]);
            const float p21 = ex2f(sf[1][1]);
            const float p30 = ex2f(sf[1][2]);
            const float p31 = ex2f(sf[1][3]);
            l0 += p00 + p01 + p20 + p21;
            l1 += p10 + p11 + p30 + p31;
            uint32_t pa[4];
            pa[0] = packbf(p00, p01);
            pa[1] = packbf(p10, p11);
            pa[2] = packbf(p20, p21);
            pa[3] = packbf(p30, p31);
            #pragma unroll
            for (int pp = 0; pp < 2; ++pp) {
                uint32_t vv[4];
                ldm_x4(vv, sV[bf] + ((pp * 16 + b_row4) * VLD + p * 16 + b_k) * 2);
                mma_bf16(Of[2 * pp],     pa, &vv[0]);
                mma_bf16(Of[2 * pp + 1], pa, &vv[2]);
            }
        }
    }

    l0 += __shfl_xor_sync(0xffffffffu, l0, 1);
    l0 += __shfl_xor_sync(0xffffffffu, l0, 2);
    l1 += __shfl_xor_sync(0xffffffffu, l1, 1);
    l1 += __shfl_xor_sync(0xffffffffu, l1, 2);

    const float i0 = 1.0f / l0, i1 = 1.0f / l1;
    const int t0 = b * NN + q0 + w * 16 + (lane >> 2);
    const int c2 = (lane & 3) * 2;
    #pragma unroll
    for (int nf = 0; nf < 4; ++nf) {
        const int d = h * HD + nf * 8 + c2;
        *reinterpret_cast<__nv_bfloat162*>(ob + (size_t)t0 * DD + d)
            = __floats2bfloat162_rn(Of[nf][0] * i0, Of[nf][1] * i0);
        *reinterpret_cast<__nv_bfloat162*>(ob + (size_t)(t0 + 8) * DD + d)
            = __floats2bfloat162_rn(Of[nf][2] * i1, Of[nf][3] * i1);
    }
}

// ---------------- merged fp32 -> bf16 conversion ----------------
#define C_X   (TT*DD/4)
#define C_QKV (3*DD*DD/4)
#define C_OUT (DD*DD/4)
#define C_W1  (DFF*DD/4)
#define CVT_TOT (C_X + C_QKV + C_OUT + 3*C_W1)
__global__ void __launch_bounds__(256) k_cvt_all(const float* __restrict__ x,
                                                 const float* __restrict__ wq,
                                                 const float* __restrict__ wo,
                                                 const float* __restrict__ w1,
                                                 const float* __restrict__ wv,
                                                 const float* __restrict__ w2) {
    int i = blockIdx.x * 256 + threadIdx.x;
    if (i >= CVT_TOT) return;
    const float* s;
    __nv_bfloat16* d;
    int o = i;
    if (o < C_X)                      { s = x;  d = xb;    }
    else if ((o -= C_X)   < C_QKV)    { s = wq; d = wqkvb; }
    else if ((o -= C_QKV) < C_OUT)    { s = wo; d = woutb; }
    else if ((o -= C_OUT) < C_W1)     { s = w1; d = w1b;   }
    else if ((o -= C_W1)  < C_W1)     { s = wv; d = wvb;   }
    else                              { o -= C_W1; s = w2; d = w2b; }
    float4 v = reinterpret_cast<const float4*>(s)[o];
    reinterpret_cast<__nv_bfloat162*>(d)[2 * o]     = __floats2bfloat162_rn(v.x, v.y);
    reinterpret_cast<__nv_bfloat162*>(d)[2 * o + 1] = __floats2bfloat162_rn(v.z, v.w);
}

// ---------------- warp-per-row Add + LayerNorm (bf16 A-operand variant) ----------------
__device__ __forceinline__ void ln_row_b(const __nv_bfloat16* __restrict__ pa,
                                         const float* __restrict__ pb,
                                         const float* __restrict__ g,
                                         const float* __restrict__ beta,
                                         float* __restrict__ out, int lane) {
    float vals[8];
    float s = 0.f, s2 = 0.f;
    #pragma unroll
    for (int i = 0; i < 8; ++i) {
        float v = __bfloat162float(pa[lane + i * 32]) + pb[lane + i * 32];
        vals[i] = v; s += v; s2 += v * v;
    }
    #pragma unroll
    for (int off = 16; off >= 1; off >>= 1) {
        s  += __shfl_xor_sync(0xffffffffu, s, off);
        s2 += __shfl_xor_sync(0xffffffffu, s2, off);
    }
    const float mean = s * (1.0f / DD);
    const float var = s2 * (1.0f / DD) - mean * mean;
    const float inv = rsqrtf(var + 1e-5f);
    #pragma unroll
    for (int i = 0; i < 8; ++i) {
        const int c = lane + i * 32;
        out[c] = (vals[i] - mean) * inv * g[c] + beta[c];
    }
}

__global__ void __launch_bounds__(256) k_ln1(const float* __restrict__ x,
                                             const float* __restrict__ g,
                                             const float* __restrict__ beta) {
    const int row = blockIdx.x * 8 + (threadIdx.x >> 5);
    const int lane = threadIdx.x & 31;
    ln_row_b(yb + (size_t)row * DD, x + (size_t)row * DD, g, beta,
             g_x1 + (size_t)row * DD, lane);
}

__global__ void __launch_bounds__(256) k_ln2(const float* __restrict__ g,
                                             const float* __restrict__ beta,
                                             float* __restrict__ out) {
    const int row = blockIdx.x * 8 + (threadIdx.x >> 5);
    const int lane = threadIdx.x & 31;
    ln_row_b(zb + (size_t)row * DD, g_x1 + (size_t)row * DD, g, beta,
             out + (size_t)row * DD, lane);
}

// ---------------- launch ----------------
extern "C" void kernel_launch(void* const* d_in, const int* in_sizes, int n_in,
                              void* d_out, int out_size) {
    const float* x     = (const float*)d_in[0];
    const float* w_qkv = (const float*)d_in[1];
    const float* w_out = (const float*)d_in[2];
    const float* b_out = (const float*)d_in[3];
    const float* w1    = (const float*)d_in[4];
    const float* wv    = (const float*)d_in[5];
    const float* w2    = (const float*)d_in[6];
    const float* ln1g  = (const float*)d_in[7];
    const float* ln1b  = (const float*)d_in[8];
    const float* ln2g  = (const float*)d_in[9];
    const float* ln2b  = (const float*)d_in[10];
    float* out = (float*)d_out;

    const int GSM = 4 * 128 * LD64 * 2;   // 73728 B (2-stage; 2 CTAs/SM)
    cudaFuncSetAttribute(k_gemm<256, 0>,  cudaFuncAttributeMaxDynamicSharedMemorySize, GSM);
    cudaFuncSetAttribute(k_gemm<256, 1>,  cudaFuncAttributeMaxDynamicSharedMemorySize, GSM);
    cudaFuncSetAttribute(k_gemm<1024, 2>, cudaFuncAttributeMaxDynamicSharedMemorySize, GSM);
    cudaFuncSetAttribute(k_ffn1,          cudaFuncAttributeMaxDynamicSharedMemorySize, GSM);

    k_cvt_all      <<<(CVT_TOT + 255) / 256, 256>>>(x, w_qkv, w_out, w1, wv, w2);
    k_gemm<256, 0> <<<dim3(3 * DD / 128, TT / 128), 256, GSM>>>(nullptr);  // QKV
    k_fattn        <<<dim3(NN / 128, HH, BB), 256>>>();                    // attention
    k_gemm<256, 1> <<<dim3(DD / 128, TT / 128), 256, GSM>>>(b_out);        // out-proj
    k_ln1          <<<TT / 8, 256>>>(x, ln1g, ln1b);
    k_ffn1         <<<dim3(DFF / 64, TT / 128), 256, GSM>>>();             // GEGLU up
    k_gemm<1024, 2><<<dim3(DD / 128, TT / 128), 256, GSM>>>(nullptr);      // FFN down
    k_ln2          <<<TT / 8, 256>>>(ln2g, ln2b, out);
}